// round 13
// baseline (speedup 1.0000x reference)
#include <cuda_runtime.h>

// Problem geometry (fixed by the reference)
#define WIDTH   1000
#define HEIGHT  1000
#define PS      5
#define NT      10
#define PPR     (WIDTH / PS)          // 200 patches per patch-row
#define NPIX    (WIDTH * HEIGHT)     // 1,000,000

constexpr int PATCHES_PER_BLOCK = 50;
constexpr int COLS_PER_BLOCK    = PATCHES_PER_BLOCK * PS;   // 250
constexpr int SEGS              = WIDTH / COLS_PER_BLOCK;   // 4
constexpr int THREADS           = 256;
constexpr int CH_VEC16          = PATCHES_PER_BLOCK * 5;    // 250 x 16B per channel

using ull = unsigned long long;

// Packed dual-FMA on the f32x2 pipe (ptxas never auto-fuses this).
__device__ __forceinline__ ull fma2(ull a, ull b, ull c) {
    ull d;
    asm("fma.rn.f32x2 %0, %1, %2, %3;" : "=l"(d) : "l"(a), "l"(b), "l"(c));
    return d;
}
__device__ __forceinline__ void unpack2(ull h, float& lo, float& hi) {
    asm("mov.b64 {%0, %1}, %2;" : "=f"(lo), "=f"(hi) : "l"(h));
}
__device__ __forceinline__ void cp_async16(void* smem_dst, const void* gmem_src) {
    unsigned saddr = (unsigned)__cvta_generic_to_shared(smem_dst);
    asm volatile("cp.async.cg.shared.global [%0], [%1], 16;" :: "r"(saddr), "l"(gmem_src));
}

__global__ __launch_bounds__(THREADS, 6)   // <=42 regs -> 6 CTAs/SM -> grid 800 one wave
void ts_approx_kernel(const float* __restrict__ pix,     // [NPIX, 2]
                      const float* __restrict__ coef,    // [NPATCH, 3, NT, 2]
                      const float* __restrict__ bias,    // [NPATCH, 3]
                      float* __restrict__ out)           // [3, NPIX]
{
    // Channel-major staging: s_coef[ch] holds 50 patches x 5 float4 = 4000 B each.
    __shared__ float4 s_coef[3][CH_VEC16];               // 12000 B

    const int b      = blockIdx.x;
    const int pr     = b / SEGS;                  // patch-row 0..199
    const int seg    = b % SEGS;                  // 0..3
    const int row0   = pr * PS;
    const int c      = threadIdx.x;               // 0..249 active
    const int patch0 = pr * PPR + seg * PATCHES_PER_BLOCK;
    const int n0     = row0 * WIDTH + seg * COLS_PER_BLOCK + c;

    // ── Pixels + bias FIRST: their DRAM latency overlaps all staging (R4/R9 order).
    const ull* __restrict__ pixq = reinterpret_cast<const ull*>(pix);
    ull xy[PS];
    float bg[3];
    if (c < COLS_PER_BLOCK) {
        #pragma unroll
        for (int r = 0; r < PS; r++)
            xy[r] = __ldcs(&pixq[n0 + r * WIDTH]);        // streaming: read-once
        const int pat = patch0 + c / PS;
        #pragma unroll
        for (int ch = 0; ch < 3; ch++)
            bg[ch] = __ldg(&bias[pat * 3 + ch]);          // 5-lane L1 broadcast
    }

    // ── Coefficients in THREE commit groups, one per channel (incremental waits).
    //    gmem per patch: [3][10][2] -> channel ch = 5 float4 at offset ch*5.
    const float4* gc = reinterpret_cast<const float4*>(coef) + (size_t)patch0 * 15;
    #pragma unroll
    for (int ch = 0; ch < 3; ch++) {
        for (int i = threadIdx.x; i < CH_VEC16; i += THREADS) {
            const int p = i / 5, k = i % 5;
            cp_async16(&s_coef[ch][i], &gc[p * 15 + ch * 5 + k]);
        }
        asm volatile("cp.async.commit_group;" ::: "memory");
    }

    const int pl = c / PS;                        // local patch 0..49

    auto do_channel = [&](int ch) {
        // 5 x LDS.128; lane stride 80B across ~7 patches/warp -> conflict-free.
        const ulonglong2* cfc = reinterpret_cast<const ulonglong2*>(&s_coef[ch][pl * 5]);
        const ulonglong2 u0 = cfc[0];   // (c0, c1) pairs (a_t, b_t)
        const ulonglong2 u1 = cfc[1];
        const ulonglong2 u2 = cfc[2];
        const ulonglong2 u3 = cfc[3];
        const ulonglong2 u4 = cfc[4];
        const float bch = bg[ch];

        // 5 independent packed Horner chains (one per row) -> ILP 5.
        #pragma unroll
        for (int r = 0; r < PS; r++) {
            ull h = u4.y;                  // (a9, b9)
            h = fma2(h, xy[r], u4.x);
            h = fma2(h, xy[r], u3.y);
            h = fma2(h, xy[r], u3.x);
            h = fma2(h, xy[r], u2.y);
            h = fma2(h, xy[r], u2.x);
            h = fma2(h, xy[r], u1.y);
            h = fma2(h, xy[r], u1.x);
            h = fma2(h, xy[r], u0.y);
            h = fma2(h, xy[r], u0.x);      // + (a0, b0)
            float hx, hy;
            unpack2(h, hx, hy);
            __stcs(&out[(size_t)ch * NPIX + n0 + r * WIDTH], hx + (hy + bch));
        }
    };

    // ── Incremental waits: compute ch0 while ch1/ch2 bytes are still in flight.
    asm volatile("cp.async.wait_group 2;" ::: "memory");
    __syncthreads();
    if (c < COLS_PER_BLOCK) do_channel(0);

    asm volatile("cp.async.wait_group 1;" ::: "memory");
    __syncthreads();
    if (c < COLS_PER_BLOCK) do_channel(1);

    asm volatile("cp.async.wait_group 0;" ::: "memory");
    __syncthreads();
    if (c < COLS_PER_BLOCK) do_channel(2);
}

extern "C" void kernel_launch(void* const* d_in, const int* in_sizes, int n_in,
                              void* d_out, int out_size)
{
    const float* pix  = (const float*)d_in[0];   // [1e6, 2]
    const float* coef = (const float*)d_in[1];   // [40000, 3, 10, 2]
    const float* bias = (const float*)d_in[2];   // [40000, 3]
    float* out        = (float*)d_out;           // [3, 1e6]

    const int nblocks = (HEIGHT / PS) * SEGS;    // 200 * 4 = 800
    ts_approx_kernel<<<nblocks, THREADS>>>(pix, coef, bias, out);
}

// round 15
// speedup vs baseline: 1.1388x; 1.1388x over previous
#include <cuda_runtime.h>

// Problem geometry (fixed by the reference)
#define WIDTH   1000
#define HEIGHT  1000
#define PS      5
#define NT      10
#define PPR     (WIDTH / PS)          // 200 patches per patch-row
#define NPIX    (WIDTH * HEIGHT)      // 1,000,000

constexpr int PATCHES_PER_BLOCK = 25;
constexpr int COLS_PER_BLOCK    = PATCHES_PER_BLOCK * PS;   // 125
constexpr int SEGS_PER_ROWSTRIP = WIDTH / COLS_PER_BLOCK;   // 8
constexpr int THREADS           = 128;
constexpr int COEF_PER_PATCH    = 3 * NT * 2;               // 60 floats = 240 B
constexpr int COEF_VEC16        = PATCHES_PER_BLOCK * COEF_PER_PATCH / 4; // 375 x 16B

using ull = unsigned long long;

// Packed dual-FMA on the f32x2 pipe (ptxas never auto-fuses this).
__device__ __forceinline__ ull fma2(ull a, ull b, ull c) {
    ull d;
    asm("fma.rn.f32x2 %0, %1, %2, %3;" : "=l"(d) : "l"(a), "l"(b), "l"(c));
    return d;
}
__device__ __forceinline__ void unpack2(ull h, float& lo, float& hi) {
    asm("mov.b64 {%0, %1}, %2;" : "=f"(lo), "=f"(hi) : "l"(h));
}
__device__ __forceinline__ void cp_async16(void* smem_dst, const void* gmem_src) {
    unsigned saddr = (unsigned)__cvta_generic_to_shared(smem_dst);
    asm volatile("cp.async.cg.shared.global [%0], [%1], 16;" :: "r"(saddr), "l"(gmem_src));
}

__global__ __launch_bounds__(THREADS)
void ts_approx_kernel(const float* __restrict__ pix,     // [NPIX, 2]
                      const float* __restrict__ coef,    // [NPATCH, 3, NT, 2]
                      const float* __restrict__ bias,    // [NPATCH, 3]
                      float* __restrict__ out)           // [3, NPIX]
{
    __shared__ float s_coef[PATCHES_PER_BLOCK * COEF_PER_PATCH]; // 6000 B
    __shared__ float s_bias[PATCHES_PER_BLOCK * 3];              // 300 B

    const int b      = blockIdx.x;
    const int pr     = b / SEGS_PER_ROWSTRIP;     // patch-row 0..199
    const int seg    = b % SEGS_PER_ROWSTRIP;     // 0..7
    const int patch0 = pr * PPR + seg * PATCHES_PER_BLOCK;

    const int c    = threadIdx.x;                 // column within strip (0..124 active)
    const int col  = seg * COLS_PER_BLOCK + c;
    const int row0 = pr * PS;
    const int n0   = row0 * WIDTH + col;

    // ── Issue the 5 pixel loads FIRST so their DRAM latency overlaps staging.
    const ull* __restrict__ pixq = reinterpret_cast<const ull*>(pix);
    ull xy[PS];
    if (c < COLS_PER_BLOCK) {
        #pragma unroll
        for (int r = 0; r < PS; r++)
            xy[r] = pixq[n0 + r * WIDTH];
    }

    // ── Stage coefficients via cp.async (no reg roundtrip, overlaps with above).
    {
        const float4* gc = reinterpret_cast<const float4*>(coef + (size_t)patch0 * COEF_PER_PATCH);
        float4* sc = reinterpret_cast<float4*>(s_coef);
        #pragma unroll
        for (int i = threadIdx.x; i < COEF_VEC16; i += THREADS)
            cp_async16(sc + i, gc + i);
        if (threadIdx.x < PATCHES_PER_BLOCK * 3)
            s_bias[threadIdx.x] = bias[patch0 * 3 + threadIdx.x];
        asm volatile("cp.async.commit_group;\n cp.async.wait_group 0;" ::: "memory");
    }
    __syncthreads();

    if (c >= COLS_PER_BLOCK) return;

    const int pl = c / PS;                        // local patch 0..24

    #pragma unroll
    for (int ch = 0; ch < 3; ch++) {
        // 10 coefficient pairs (a_t,b_t): 5 x 16B smem loads, lane stride 240B
        // across ~7 distinct patches per warp -> conflict-free.
        const ulonglong2* cfc =
            reinterpret_cast<const ulonglong2*>(s_coef) + pl * 15 + ch * 5;
        const ulonglong2 u0 = cfc[0];   // (c0, c1)
        const ulonglong2 u1 = cfc[1];   // (c2, c3)
        const ulonglong2 u2 = cfc[2];   // (c4, c5)
        const ulonglong2 u3 = cfc[3];   // (c6, c7)
        const ulonglong2 u4 = cfc[4];   // (c8, c9)
        const float bch = s_bias[pl * 3 + ch];

        // 5 independent packed Horner chains (one per row) -> ILP 5.
        #pragma unroll
        for (int r = 0; r < PS; r++) {
            ull h = u4.y;                  // (a9, b9)
            h = fma2(h, xy[r], u4.x);
            h = fma2(h, xy[r], u3.y);
            h = fma2(h, xy[r], u3.x);
            h = fma2(h, xy[r], u2.y);
            h = fma2(h, xy[r], u2.x);
            h = fma2(h, xy[r], u1.y);
            h = fma2(h, xy[r], u1.x);
            h = fma2(h, xy[r], u0.y);
            h = fma2(h, xy[r], u0.x);      // + (a0, b0)
            float hx, hy;
            unpack2(h, hx, hy);
            out[(size_t)ch * NPIX + n0 + r * WIDTH] = hx + (hy + bch);
        }
    }
}

extern "C" void kernel_launch(void* const* d_in, const int* in_sizes, int n_in,
                              void* d_out, int out_size)
{
    const float* pix  = (const float*)d_in[0];   // [1e6, 2]
    const float* coef = (const float*)d_in[1];   // [40000, 3, 10, 2]
    const float* bias = (const float*)d_in[2];   // [40000, 3]
    float* out        = (float*)d_out;           // [3, 1e6]

    const int nblocks = (HEIGHT / PS) * SEGS_PER_ROWSTRIP;   // 200 * 8 = 1600
    ts_approx_kernel<<<nblocks, THREADS>>>(pix, coef, bias, out);
}